// round 16
// baseline (speedup 1.0000x reference)
#include <cuda_runtime.h>
#include <cuda_fp16.h>
#include <cstdint>
#include <math.h>

#define BB 8
#define NSEQ 2048
#define DDIM 512
#define MFLAT (BB*NSEQ)

// ---------------- scratch (device globals: allocation-free) ----------------
__device__ __half g_qry[MFLAT*DDIM], g_ctx[MFLAT*DDIM];
__device__ __half g_wq[DDIM*DDIM], g_wo[DDIM*DDIM];
__device__ __half g_wvT[DDIM*DDIM];          // Wv transposed
__device__ __half g_wp[DDIM*DDIM];           // W' = Wo @ Wv
__device__ float  g_b2[DDIM];                // b'' = Wo@bv + bo
__device__ __half g_q[MFLAT*DDIM];
__device__ __half g_uT[MFLAT*DDIM];          // u^T per batch [DDIM, NSEQ]
__device__ __half g_s[(size_t)BB*NSEQ*NSEQ]; // fp16 scores
__device__ __half g_attn[(size_t)BB*NSEQ*NSEQ];

// ---------------- helpers ----------------
__device__ __forceinline__ uint32_t smem_u32(const void* p){
    uint32_t a;
    asm("{ .reg .u64 t; cvta.to.shared.u64 t, %1; cvt.u32.u64 %0, t; }" : "=r"(a) : "l"(p));
    return a;
}

#define CP_ASYNC16(sm, gm) \
    asm volatile("cp.async.cg.shared.global [%0], [%1], 16;" :: "r"(sm), "l"(gm))
#define CP_COMMIT() asm volatile("cp.async.commit_group;" ::: "memory")
#define CP_WAIT2()  asm volatile("cp.async.wait_group 2;" ::: "memory")
#define CP_WAIT1()  asm volatile("cp.async.wait_group 1;" ::: "memory")
#define CP_WAIT0()  asm volatile("cp.async.wait_group 0;" ::: "memory")

__device__ __forceinline__ void ldmatrix_x4(uint32_t& r0, uint32_t& r1, uint32_t& r2, uint32_t& r3, uint32_t addr){
    asm volatile("ldmatrix.sync.aligned.m8n8.x4.shared.b16 {%0,%1,%2,%3}, [%4];"
        : "=r"(r0), "=r"(r1), "=r"(r2), "=r"(r3) : "r"(addr));
}
__device__ __forceinline__ void mma_f16(float* c, const uint32_t* a, const uint32_t* b){
    asm volatile(
        "mma.sync.aligned.m16n8k16.row.col.f32.f16.f16.f32 "
        "{%0,%1,%2,%3}, {%4,%5,%6,%7}, {%8,%9}, {%0,%1,%2,%3};"
        : "+f"(c[0]), "+f"(c[1]), "+f"(c[2]), "+f"(c[3])
        : "r"(a[0]), "r"(a[1]), "r"(a[2]), "r"(a[3]), "r"(b[0]), "r"(b[1]));
}

// ---------------- GEMM config (CTA tile 128x64, warp tile 64x16, BK=32, 4 stages) ----------------
// 3 CTAs/SM (24 warps): attacks the 16-warp stall plateau.
#define PITCH 80
#define ATILEB (128*PITCH)           // 10240 B
#define BTILEB (64*PITCH)            // 5120 B
#define STAGEB (ATILEB+BTILEB)       // 15360 B
#define NSTAGE 4
#define SMEM_G (NSTAGE*STAGEB)       // 61440 B -> 3 CTAs/SM

// Mainloop: acc += A @ B^T (single product). One __syncthreads per iter.
#define GEMM_MAINLOOP(Aop, Bop, Kdim)                                                \
    const int T = (Kdim) >> 5;                                                       \
    const int aRow = tid >> 1;                                                       \
    const int aOff = (tid & 1) * 32;                                                 \
    const int bRow = tid >> 2;                                                       \
    const int bOff = (tid & 3) * 16;                                                 \
    auto issue = [&](int t){                                                         \
        const int st = t & 3;                                                        \
        const int kk = t << 5;                                                       \
        const __half* Ap = (Aop) + (long)(rowBase + aRow) * (Kdim) + kk + (aOff >> 1); \
        const uint32_t sa = smBase + st * STAGEB + aRow * PITCH + aOff;              \
        CP_ASYNC16(sa,      Ap);                                                     \
        CP_ASYNC16(sa + 16, Ap + 8);                                                 \
        const __half* Bp = (Bop) + (long)(colBase + bRow) * (Kdim) + kk + (bOff >> 1); \
        const uint32_t sb = smBase + st * STAGEB + ATILEB + bRow * PITCH + bOff;     \
        CP_ASYNC16(sb, Bp);                                                          \
        CP_COMMIT();                                                                 \
    };                                                                               \
    issue(0); issue(1); issue(2);                                                    \
    const uint32_t aLaneOff = (uint32_t)(warpM*64 + (lane & 15)) * PITCH + ((lane >> 4) & 1) * 16; \
    const uint32_t bLaneOff = (uint32_t)(warpN*16 + (lane & 7) + ((lane >> 4) & 1) * 8) * PITCH    \
                            + ((lane >> 3) & 1) * 16;                                \
    for (int t = 0; t < T; t++) {                                                    \
        const int rem = T - 1 - t;                                                   \
        if (rem >= 2) { CP_WAIT2(); } else if (rem == 1) { CP_WAIT1(); } else { CP_WAIT0(); } \
        __syncthreads();                                                             \
        if (t + 3 < T) issue(t + 3);                                                 \
        const int st = t & 3;                                                        \
        const uint32_t aBase = smBase + st * STAGEB + aLaneOff;                      \
        const uint32_t bBase = smBase + st * STAGEB + ATILEB + bLaneOff;             \
        _Pragma("unroll")                                                            \
        for (int ks = 0; ks < 2; ks++) {                                             \
            const uint32_t kByte = ks * 32;                                          \
            uint32_t afr[4][4];                                                      \
            _Pragma("unroll")                                                        \
            for (int mt = 0; mt < 4; mt++)                                           \
                ldmatrix_x4(afr[mt][0], afr[mt][1], afr[mt][2], afr[mt][3],          \
                            aBase + mt * 16 * PITCH + kByte);                        \
            uint32_t bfr[4];                                                         \
            ldmatrix_x4(bfr[0], bfr[1], bfr[2], bfr[3], bBase + kByte);              \
            _Pragma("unroll")                                                        \
            for (int mt = 0; mt < 4; mt++)                                           \
                _Pragma("unroll")                                                    \
                for (int nt = 0; nt < 2; nt++)                                       \
                    mma_f16(acc[mt][nt], afr[mt], &bfr[nt * 2]);                     \
        }                                                                            \
    }

// ---------------- generic GEMM ----------------
// MODE 0: fp32 out (+bias, alpha). MODE 1: rounded fp16 out (alpha applied).
template<int MODE>
__global__ __launch_bounds__(256, 3)
void mma_gemm(const __half* __restrict__ A, const __half* __restrict__ B,
              const float* __restrict__ bias,
              float* __restrict__ outF, __half* __restrict__ outH,
              int M, int N, int K, float alpha,
              long sA, long sB, long sC)
{
    extern __shared__ __align__(128) char smem[];
    const int tid  = threadIdx.x;
    const int warp = tid >> 5;
    const int lane = tid & 31;
    const int warpM = warp >> 2;   // 0..1 (64 rows)
    const int warpN = warp & 3;    // 0..3 (16 cols)

    const int z = blockIdx.z;
    A += (long)z * sA;
    B += (long)z * sB;
    if (MODE == 0) { outF += (long)z * sC; } else { outH += (long)z * sC; }

    const int rowBase = blockIdx.y * 128;
    const int colBase = blockIdx.x * 64;
    const uint32_t smBase = smem_u32(smem);

    float acc[4][2][4];
    #pragma unroll
    for (int i = 0; i < 4; i++)
        #pragma unroll
        for (int j = 0; j < 2; j++)
            #pragma unroll
            for (int c = 0; c < 4; c++) acc[i][j][c] = 0.f;

    GEMM_MAINLOOP(A, B, K)

    #pragma unroll
    for (int mt = 0; mt < 4; mt++) {
        const int r0 = rowBase + warpM*64 + mt*16 + (lane >> 2);
        #pragma unroll
        for (int nt = 0; nt < 2; nt++) {
            const int gc = colBase + warpN*16 + nt*8 + (lane & 3)*2;
            float v00 = acc[mt][nt][0] * alpha;
            float v01 = acc[mt][nt][1] * alpha;
            float v10 = acc[mt][nt][2] * alpha;
            float v11 = acc[mt][nt][3] * alpha;
            if (bias) {
                const float b0 = bias[gc], b1 = bias[gc+1];
                v00 += b0; v01 += b1; v10 += b0; v11 += b1;
            }
            if (MODE == 0) {
                *(float2*)&outF[(long)r0 * N + gc]       = make_float2(v00, v01);
                *(float2*)&outF[(long)(r0+8) * N + gc]   = make_float2(v10, v11);
            } else {
                __half2 h;
                h.x = __float2half(v00); h.y = __float2half(v01);
                *(__half2*)&outH[(long)r0 * N + gc] = h;
                h.x = __float2half(v10); h.y = __float2half(v11);
                *(__half2*)&outH[(long)(r0+8) * N + gc] = h;
            }
        }
    }
}

// ---------------- combined Q/U projection (z=0: q rounded out, z=1: u^T rounded out) ----------
__global__ __launch_bounds__(256, 3)
void qu_gemm(const __half* __restrict__ qry, const __half* __restrict__ wq,
             const float* __restrict__ bq, __half* __restrict__ q,
             const __half* __restrict__ ctx, const __half* __restrict__ wp,
             __half* __restrict__ ut)
{
    extern __shared__ __align__(128) char smem[];
    const int tid  = threadIdx.x;
    const int warp = tid >> 5;
    const int lane = tid & 31;
    const int warpM = warp >> 2;
    const int warpN = warp & 3;
    const int isU = blockIdx.z;

    const int rowBase = blockIdx.y * 128;
    const int colBase = blockIdx.x * 64;
    const uint32_t smBase = smem_u32(smem);

    const __half* A = isU ? ctx : qry;
    const __half* B = isU ? wp  : wq;

    float acc[4][2][4];
    #pragma unroll
    for (int i = 0; i < 4; i++)
        #pragma unroll
        for (int j = 0; j < 2; j++)
            #pragma unroll
            for (int c = 0; c < 4; c++) acc[i][j][c] = 0.f;

    GEMM_MAINLOOP(A, B, DDIM)

    #pragma unroll
    for (int mt = 0; mt < 4; mt++) {
        const int r0 = rowBase + warpM*64 + mt*16 + (lane >> 2);
        #pragma unroll
        for (int nt = 0; nt < 2; nt++) {
            const int gc = colBase + warpN*16 + nt*8 + (lane & 3)*2;
            float v00 = acc[mt][nt][0];
            float v01 = acc[mt][nt][1];
            float v10 = acc[mt][nt][2];
            float v11 = acc[mt][nt][3];
            if (!isU) {        // q = round(... + bq), row-major
                const float b0 = bq[gc], b1 = bq[gc+1];
                v00 += b0; v01 += b1; v10 += b0; v11 += b1;
                __half2 h;
                h.x = __float2half(v00); h.y = __float2half(v01);
                *(__half2*)&q[(long)r0 * DDIM + gc] = h;
                h.x = __float2half(v10); h.y = __float2half(v11);
                *(__half2*)&q[(long)(r0+8) * DDIM + gc] = h;
            } else {           // u^T per batch [DDIM, NSEQ], rounded fp16
                const int rows[2] = {r0, r0 + 8};
                const float vals[2][2] = {{v00, v01}, {v10, v11}};
                #pragma unroll
                for (int rr = 0; rr < 2; rr++) {
                    const int bb = rows[rr] >> 11, tok = rows[rr] & 2047;
                    const long base = (long)bb * (DDIM * NSEQ) + tok;
                    #pragma unroll
                    for (int cc = 0; cc < 2; cc++)
                        ut[base + (long)(gc + cc) * NSEQ] = __float2half(vals[rr][cc]);
                }
            }
        }
    }
}

// ---------------- fused input round (fp32 -> fp16); Wv also written transposed ----------------
#define NQ4 ((MFLAT*DDIM)/4)
#define NW4 ((DDIM*DDIM)/4)
__global__ __launch_bounds__(256)
void round_all_kernel(const float* __restrict__ query, const float* __restrict__ context,
                      const float* __restrict__ Wq, const float* __restrict__ Wv, const float* __restrict__ Wo,
                      __half* __restrict__ qry, __half* __restrict__ ctx,
                      __half* __restrict__ wq, __half* __restrict__ wvT, __half* __restrict__ wo)
{
    int i = blockIdx.x * blockDim.x + threadIdx.x;
    const float* src; __half* dst; int mode = 0;
    if (i < NQ4)                  { src = query;   dst = qry; }
    else if ((i -= NQ4) < NQ4)    { src = context; dst = ctx; }
    else if ((i -= NQ4) < NW4)    { src = Wq;      dst = wq; }
    else if ((i -= NW4) < NW4)    { src = Wv;      dst = wvT; mode = 1; }
    else if ((i -= NW4) < NW4)    { src = Wo;      dst = wo; }
    else return;
    float4 v = ((const float4*)src)[i];
    if (mode == 0) {
        __half2 h0, h1;
        h0.x = __float2half(v.x); h0.y = __float2half(v.y);
        h1.x = __float2half(v.z); h1.y = __float2half(v.w);
        ((__half2*)dst)[2*i]   = h0;
        ((__half2*)dst)[2*i+1] = h1;
    } else {
        const int f  = (4*i) >> 9;
        const int d0 = (4*i) & 511;
        dst[(long)(d0+0) * DDIM + f] = __float2half(v.x);
        dst[(long)(d0+1) * DDIM + f] = __float2half(v.y);
        dst[(long)(d0+2) * DDIM + f] = __float2half(v.z);
        dst[(long)(d0+3) * DDIM + f] = __float2half(v.w);
    }
}

// ---------------- b'' = Wo @ bv + bo (512 blocks x 128 threads) ----------------
__global__ __launch_bounds__(128)
void bias_fold_kernel(const float* __restrict__ Wo, const float* __restrict__ bv,
                      const float* __restrict__ bo, float* __restrict__ b2)
{
    const int e = blockIdx.x;
    const int tid = threadIdx.x;
    __shared__ float red[128];
    float s = 0.f;
    for (int f = tid; f < DDIM; f += 128)
        s += Wo[(long)e * DDIM + f] * bv[f];
    red[tid] = s; __syncthreads();
    for (int o = 64; o > 0; o >>= 1) {
        if (tid < o) red[tid] += red[tid + o];
        __syncthreads();
    }
    if (tid == 0) b2[e] = red[0] + bo[e];
}

// ---------------- softmax over fp16 scores -> rounded fp16 attn ----------------
__global__ __launch_bounds__(256)
void softmax_round_kernel(const __half* __restrict__ s, __half* __restrict__ attn)
{
    const long rbase = (long)blockIdx.x * NSEQ;
    const int tid = threadIdx.x;
    const int warp = tid >> 5, lane = tid & 31;
    __shared__ float red[8];

    uint4 raw = ((const uint4*)(s + rbase))[tid];
    __half2 hx[4];
    hx[0] = *(__half2*)&raw.x; hx[1] = *(__half2*)&raw.y;
    hx[2] = *(__half2*)&raw.z; hx[3] = *(__half2*)&raw.w;
    float x[8];
    #pragma unroll
    for (int j = 0; j < 4; j++) {
        float2 f = __half22float2(hx[j]);
        x[2*j] = f.x; x[2*j+1] = f.y;
    }

    float m = x[0];
    #pragma unroll
    for (int j = 1; j < 8; j++) m = fmaxf(m, x[j]);
    #pragma unroll
    for (int o = 16; o > 0; o >>= 1) m = fmaxf(m, __shfl_xor_sync(0xFFFFFFFF, m, o));
    if (lane == 0) red[warp] = m;
    __syncthreads();
    m = red[lane & 7];
    #pragma unroll
    for (int o = 4; o > 0; o >>= 1) m = fmaxf(m, __shfl_xor_sync(0xFFFFFFFF, m, o));

    float sum = 0.f;
    #pragma unroll
    for (int j = 0; j < 8; j++) { x[j] = __expf(x[j] - m); sum += x[j]; }
    #pragma unroll
    for (int o = 16; o > 0; o >>= 1) sum += __shfl_xor_sync(0xFFFFFFFF, sum, o);
    __syncthreads();
    if (lane == 0) red[warp] = sum;
    __syncthreads();
    sum = red[lane & 7];
    #pragma unroll
    for (int o = 4; o > 0; o >>= 1) sum += __shfl_xor_sync(0xFFFFFFFF, sum, o);
    const float inv = 1.f / sum;

    __half2 h[4];
    #pragma unroll
    for (int j = 0; j < 4; j++) {
        h[j].x = __float2half(x[2*j]   * inv);
        h[j].y = __float2half(x[2*j+1] * inv);
    }
    uint4 outv;
    outv.x = *(uint32_t*)&h[0]; outv.y = *(uint32_t*)&h[1];
    outv.z = *(uint32_t*)&h[2]; outv.w = *(uint32_t*)&h[3];
    ((uint4*)(attn + rbase))[tid] = outv;
}

// ---------------- launch ----------------
extern "C" void kernel_launch(void* const* d_in, const int* in_sizes, int n_in,
                              void* d_out, int out_size)
{
    (void)in_sizes; (void)n_in; (void)out_size;
    const float* query   = (const float*)d_in[0];
    const float* context = (const float*)d_in[1];
    const float* Wq      = (const float*)d_in[2];
    const float* bq      = (const float*)d_in[3];
    const float* Wv      = (const float*)d_in[4];
    const float* bv      = (const float*)d_in[5];
    const float* Wo      = (const float*)d_in[6];
    const float* bo      = (const float*)d_in[7];
    float* out = (float*)d_out;

    __half *qry,*ctx,*wq,*wvT,*wo,*wp,*q,*uT,*attn,*s;
    float *b2;
    cudaGetSymbolAddress((void**)&qry, g_qry);
    cudaGetSymbolAddress((void**)&ctx, g_ctx);
    cudaGetSymbolAddress((void**)&wq,  g_wq);
    cudaGetSymbolAddress((void**)&wvT, g_wvT);
    cudaGetSymbolAddress((void**)&wo,  g_wo);
    cudaGetSymbolAddress((void**)&wp,  g_wp);
    cudaGetSymbolAddress((void**)&q,   g_q);
    cudaGetSymbolAddress((void**)&uT,  g_uT);
    cudaGetSymbolAddress((void**)&attn,g_attn);
    cudaGetSymbolAddress((void**)&s,   g_s);
    cudaGetSymbolAddress((void**)&b2,  g_b2);

    cudaFuncSetAttribute((const void*)mma_gemm<0>, cudaFuncAttributeMaxDynamicSharedMemorySize, SMEM_G);
    cudaFuncSetAttribute((const void*)mma_gemm<1>, cudaFuncAttributeMaxDynamicSharedMemorySize, SMEM_G);
    cudaFuncSetAttribute((const void*)qu_gemm,     cudaFuncAttributeMaxDynamicSharedMemorySize, SMEM_G);

    const float scale = 1.0f / sqrtf((float)DDIM);

    // 0) round all fp32 inputs -> fp16 (Wv written transposed)
    {
        int total = 2 * NQ4 + 3 * NW4;
        round_all_kernel<<<(total + 255) / 256, 256>>>(
            query, context, Wq, Wv, Wo,
            qry, ctx, wq, wvT, wo);
    }

    // 0b) W' = Wo @ Wv  (tiny GEMM: A=wo [e,f], B=wvT [d,f] -> W'[e,d])
    mma_gemm<1><<<dim3(DDIM/64, DDIM/128, 1), 256, SMEM_G>>>(
        wo, wvT, nullptr, nullptr, wp,
        DDIM, DDIM, DDIM, 1.0f, 0, 0, 0);

    // 0c) b'' = Wo @ bv + bo
    bias_fold_kernel<<<DDIM, 128>>>(Wo, bv, bo, b2);

    // 1+2) q = round(qry@Wq^T + bq)  AND  u^T = round((ctx@W'^T)^T)
    qu_gemm<<<dim3(DDIM/64, MFLAT/128, 2), 256, SMEM_G>>>(
        qry, wq, bq, q, ctx, wp, uT);

    // 3) scores = round_fp16(scale * q @ ctx^T)  (batched)
    mma_gemm<1><<<dim3(NSEQ/64, NSEQ/128, BB), 256, SMEM_G>>>(
        q, ctx, nullptr, nullptr, s,
        NSEQ, NSEQ, DDIM, scale,
        (long)NSEQ * DDIM, (long)NSEQ * DDIM, (long)NSEQ * NSEQ);

    // 4) softmax rows (fp16 in) -> rounded fp16 attn
    softmax_round_kernel<<<BB * NSEQ, 256>>>(s, attn);

    // 5) out = attn @ (u^T)^T + b''  (batched) -> fp32 out directly
    mma_gemm<0><<<dim3(DDIM/64, NSEQ/128, BB), 256, SMEM_G>>>(
        attn, uT, b2, out, nullptr,
        NSEQ, DDIM, NSEQ, 1.0f,
        (long)NSEQ * NSEQ, (long)DDIM * NSEQ, (long)NSEQ * DDIM);
}

// round 17
// speedup vs baseline: 1.1628x; 1.1628x over previous
#include <cuda_runtime.h>
#include <cuda_fp16.h>
#include <cstdint>
#include <math.h>

#define BB 8
#define NSEQ 2048
#define DDIM 512
#define MFLAT (BB*NSEQ)

// ---------------- scratch (device globals: allocation-free) ----------------
__device__ __half g_qry[MFLAT*DDIM], g_ctx[MFLAT*DDIM];
__device__ __half g_wq[DDIM*DDIM], g_wo[DDIM*DDIM];
__device__ __half g_wvT[DDIM*DDIM];          // Wv transposed
__device__ __half g_wp[DDIM*DDIM];           // W' = Wo @ Wv
__device__ float  g_b2[DDIM];                // b'' = Wo@bv + bo
__device__ __half g_q[MFLAT*DDIM];
__device__ __half g_uT[MFLAT*DDIM];          // u^T per batch [DDIM, NSEQ]
__device__ __half g_s[(size_t)BB*NSEQ*NSEQ]; // fp16 scores
__device__ __half g_attn[(size_t)BB*NSEQ*NSEQ];

// ---------------- helpers ----------------
__device__ __forceinline__ uint32_t smem_u32(const void* p){
    uint32_t a;
    asm("{ .reg .u64 t; cvta.to.shared.u64 t, %1; cvt.u32.u64 %0, t; }" : "=r"(a) : "l"(p));
    return a;
}

#define CP_ASYNC16(sm, gm) \
    asm volatile("cp.async.cg.shared.global [%0], [%1], 16;" :: "r"(sm), "l"(gm))
#define CP_COMMIT() asm volatile("cp.async.commit_group;" ::: "memory")
#define CP_WAIT2()  asm volatile("cp.async.wait_group 2;" ::: "memory")
#define CP_WAIT1()  asm volatile("cp.async.wait_group 1;" ::: "memory")
#define CP_WAIT0()  asm volatile("cp.async.wait_group 0;" ::: "memory")

__device__ __forceinline__ void ldmatrix_x4(uint32_t& r0, uint32_t& r1, uint32_t& r2, uint32_t& r3, uint32_t addr){
    asm volatile("ldmatrix.sync.aligned.m8n8.x4.shared.b16 {%0,%1,%2,%3}, [%4];"
        : "=r"(r0), "=r"(r1), "=r"(r2), "=r"(r3) : "r"(addr));
}
__device__ __forceinline__ void mma_f16(float* c, const uint32_t* a, const uint32_t* b){
    asm volatile(
        "mma.sync.aligned.m16n8k16.row.col.f32.f16.f16.f32 "
        "{%0,%1,%2,%3}, {%4,%5,%6,%7}, {%8,%9}, {%0,%1,%2,%3};"
        : "+f"(c[0]), "+f"(c[1]), "+f"(c[2]), "+f"(c[3])
        : "r"(a[0]), "r"(a[1]), "r"(a[2]), "r"(a[3]), "r"(b[0]), "r"(b[1]));
}

// ---------------- GEMM config (CTA 128x128, warp 64x32, BK=32, 4 stages) ----------------
#define PITCH 80
#define TILEB (128*PITCH)
#define STAGEB (2*TILEB)
#define NSTAGE 4
#define SMEM_G (NSTAGE*STAGEB)     // 81920 B -> 2 CTAs/SM

// Mainloop: acc += A @ B^T (single product). One __syncthreads per iter.
#define GEMM_MAINLOOP(Aop, Bop, Kdim)                                                \
    const int T = (Kdim) >> 5;                                                       \
    const int ldRow = tid >> 1;                                                      \
    const int ldOff = (tid & 1) * 32;                                                \
    auto issue = [&](int t){                                                         \
        const int st = t & 3;                                                        \
        const int kk = t << 5;                                                       \
        const __half* Ap = (Aop) + (long)(rowBase + ldRow) * (Kdim) + kk + (ldOff >> 1); \
        const __half* Bp = (Bop) + (long)(colBase + ldRow) * (Kdim) + kk + (ldOff >> 1); \
        const uint32_t sa = smBase + st * STAGEB + ldRow * PITCH + ldOff;            \
        const uint32_t sb = sa + TILEB;                                              \
        CP_ASYNC16(sa,      Ap);                                                     \
        CP_ASYNC16(sa + 16, Ap + 8);                                                 \
        CP_ASYNC16(sb,      Bp);                                                     \
        CP_ASYNC16(sb + 16, Bp + 8);                                                 \
        CP_COMMIT();                                                                 \
    };                                                                               \
    issue(0); issue(1); issue(2);                                                    \
    const uint32_t aLaneOff = (uint32_t)(warpM*64 + (lane & 15)) * PITCH + ((lane >> 4) & 1) * 16; \
    const uint32_t bLaneOff = (uint32_t)(warpN*32 + (lane & 7) + ((lane >> 4) & 1) * 8) * PITCH    \
                            + ((lane >> 3) & 1) * 16;                                \
    for (int t = 0; t < T; t++) {                                                    \
        const int rem = T - 1 - t;                                                   \
        if (rem >= 2) { CP_WAIT2(); } else if (rem == 1) { CP_WAIT1(); } else { CP_WAIT0(); } \
        __syncthreads();                                                             \
        if (t + 3 < T) issue(t + 3);                                                 \
        const int st = t & 3;                                                        \
        const uint32_t aBase = smBase + st * STAGEB + aLaneOff;                      \
        const uint32_t bBase = smBase + st * STAGEB + TILEB + bLaneOff;              \
        _Pragma("unroll")                                                            \
        for (int ks = 0; ks < 2; ks++) {                                             \
            const uint32_t kByte = ks * 32;                                          \
            uint32_t afr[4][4];                                                      \
            _Pragma("unroll")                                                        \
            for (int mt = 0; mt < 4; mt++)                                           \
                ldmatrix_x4(afr[mt][0], afr[mt][1], afr[mt][2], afr[mt][3],          \
                            aBase + mt * 16 * PITCH + kByte);                        \
            uint32_t bfr[2][4];                                                      \
            _Pragma("unroll")                                                        \
            for (int p = 0; p < 2; p++)                                              \
                ldmatrix_x4(bfr[p][0], bfr[p][1], bfr[p][2], bfr[p][3],              \
                            bBase + p * 16 * PITCH + kByte);                         \
            _Pragma("unroll")                                                        \
            for (int mt = 0; mt < 4; mt++)                                           \
                _Pragma("unroll")                                                    \
                for (int nt = 0; nt < 4; nt++)                                       \
                    mma_f16(acc[mt][nt], afr[mt], &bfr[nt >> 1][(nt & 1) * 2]);      \
        }                                                                            \
    }

// ---------------- generic GEMM ----------------
// MODE 0: fp32 out (+bias, alpha). MODE 1: rounded fp16 out (alpha+bias applied).
template<int MODE>
__global__ __launch_bounds__(256, 2)
void mma_gemm(const __half* __restrict__ A, const __half* __restrict__ B,
              const float* __restrict__ bias,
              float* __restrict__ outF, __half* __restrict__ outH,
              int M, int N, int K, float alpha,
              long sA, long sB, long sC)
{
    extern __shared__ __align__(128) char smem[];
    const int tid  = threadIdx.x;
    const int warp = tid >> 5;
    const int lane = tid & 31;
    const int warpM = warp >> 2;
    const int warpN = warp & 3;

    const int z = blockIdx.z;
    A += (long)z * sA;
    B += (long)z * sB;
    if (MODE == 0) { outF += (long)z * sC; } else { outH += (long)z * sC; }

    const int rowBase = blockIdx.y * 128;
    const int colBase = blockIdx.x * 128;
    const uint32_t smBase = smem_u32(smem);

    float acc[4][4][4];
    #pragma unroll
    for (int i = 0; i < 4; i++)
        #pragma unroll
        for (int j = 0; j < 4; j++)
            #pragma unroll
            for (int c = 0; c < 4; c++) acc[i][j][c] = 0.f;

    GEMM_MAINLOOP(A, B, K)

    #pragma unroll
    for (int mt = 0; mt < 4; mt++) {
        const int r0 = rowBase + warpM*64 + mt*16 + (lane >> 2);
        #pragma unroll
        for (int nt = 0; nt < 4; nt++) {
            const int gc = colBase + warpN*32 + nt*8 + (lane & 3)*2;
            float v00 = acc[mt][nt][0] * alpha;
            float v01 = acc[mt][nt][1] * alpha;
            float v10 = acc[mt][nt][2] * alpha;
            float v11 = acc[mt][nt][3] * alpha;
            if (bias) {
                const float b0 = bias[gc], b1 = bias[gc+1];
                v00 += b0; v01 += b1; v10 += b0; v11 += b1;
            }
            if (MODE == 0) {
                *(float2*)&outF[(long)r0 * N + gc]       = make_float2(v00, v01);
                *(float2*)&outF[(long)(r0+8) * N + gc]   = make_float2(v10, v11);
            } else {
                __half2 h;
                h.x = __float2half(v00); h.y = __float2half(v01);
                *(__half2*)&outH[(long)r0 * N + gc] = h;
                h.x = __float2half(v10); h.y = __float2half(v11);
                *(__half2*)&outH[(long)(r0+8) * N + gc] = h;
            }
        }
    }
}

// ---------------- u projection: u = ctx @ W'^T, stored transposed per batch ----------------
__global__ __launch_bounds__(256, 2)
void u_gemm(const __half* __restrict__ ctx, const __half* __restrict__ wp,
            __half* __restrict__ ut)
{
    extern __shared__ __align__(128) char smem[];
    const int tid  = threadIdx.x;
    const int warp = tid >> 5;
    const int lane = tid & 31;
    const int warpM = warp >> 2;
    const int warpN = warp & 3;

    const int rowBase = blockIdx.y * 128;
    const int colBase = blockIdx.x * 128;
    const uint32_t smBase = smem_u32(smem);

    float acc[4][4][4];
    #pragma unroll
    for (int i = 0; i < 4; i++)
        #pragma unroll
        for (int j = 0; j < 4; j++)
            #pragma unroll
            for (int c = 0; c < 4; c++) acc[i][j][c] = 0.f;

    GEMM_MAINLOOP(ctx, wp, DDIM)

    #pragma unroll
    for (int mt = 0; mt < 4; mt++) {
        const int r0 = rowBase + warpM*64 + mt*16 + (lane >> 2);
        #pragma unroll
        for (int nt = 0; nt < 4; nt++) {
            const int gc = colBase + warpN*32 + nt*8 + (lane & 3)*2;
            const float vals[2][2] = {{acc[mt][nt][0], acc[mt][nt][1]},
                                      {acc[mt][nt][2], acc[mt][nt][3]}};
            const int rows[2] = {r0, r0 + 8};
            #pragma unroll
            for (int rr = 0; rr < 2; rr++) {
                const int bb = rows[rr] >> 11, tok = rows[rr] & 2047;
                const long base = (long)bb * (DDIM * NSEQ) + tok;
                #pragma unroll
                for (int cc = 0; cc < 2; cc++)
                    ut[base + (long)(gc + cc) * NSEQ] = __float2half(vals[rr][cc]);
            }
        }
    }
}

// ---------------- fused input round (fp32 -> fp16); Wv also written transposed ----------------
#define NQ4 ((MFLAT*DDIM)/4)
#define NW4 ((DDIM*DDIM)/4)
__global__ __launch_bounds__(256)
void round_all_kernel(const float* __restrict__ query, const float* __restrict__ context,
                      const float* __restrict__ Wq, const float* __restrict__ Wv, const float* __restrict__ Wo,
                      __half* __restrict__ qry, __half* __restrict__ ctx,
                      __half* __restrict__ wq, __half* __restrict__ wvT, __half* __restrict__ wo)
{
    int i = blockIdx.x * blockDim.x + threadIdx.x;
    const float* src; __half* dst; int mode = 0;
    if (i < NQ4)                  { src = query;   dst = qry; }
    else if ((i -= NQ4) < NQ4)    { src = context; dst = ctx; }
    else if ((i -= NQ4) < NW4)    { src = Wq;      dst = wq; }
    else if ((i -= NW4) < NW4)    { src = Wv;      dst = wvT; mode = 1; }
    else if ((i -= NW4) < NW4)    { src = Wo;      dst = wo; }
    else return;
    float4 v = ((const float4*)src)[i];
    if (mode == 0) {
        __half2 h0, h1;
        h0.x = __float2half(v.x); h0.y = __float2half(v.y);
        h1.x = __float2half(v.z); h1.y = __float2half(v.w);
        ((__half2*)dst)[2*i]   = h0;
        ((__half2*)dst)[2*i+1] = h1;
    } else {
        const int f  = (4*i) >> 9;
        const int d0 = (4*i) & 511;
        dst[(long)(d0+0) * DDIM + f] = __float2half(v.x);
        dst[(long)(d0+1) * DDIM + f] = __float2half(v.y);
        dst[(long)(d0+2) * DDIM + f] = __float2half(v.z);
        dst[(long)(d0+3) * DDIM + f] = __float2half(v.w);
    }
}

// ---------------- b'' = Wo @ bv + bo (512 blocks x 128 threads) ----------------
__global__ __launch_bounds__(128)
void bias_fold_kernel(const float* __restrict__ Wo, const float* __restrict__ bv,
                      const float* __restrict__ bo, float* __restrict__ b2)
{
    const int e = blockIdx.x;
    const int tid = threadIdx.x;
    __shared__ float red[128];
    float s = 0.f;
    for (int f = tid; f < DDIM; f += 128)
        s += Wo[(long)e * DDIM + f] * bv[f];
    red[tid] = s; __syncthreads();
    for (int o = 64; o > 0; o >>= 1) {
        if (tid < o) red[tid] += red[tid + o];
        __syncthreads();
    }
    if (tid == 0) b2[e] = red[0] + bo[e];
}

// ---------------- softmax over fp16 scores -> rounded fp16 attn ----------------
__global__ __launch_bounds__(256)
void softmax_round_kernel(const __half* __restrict__ s, __half* __restrict__ attn)
{
    const long rbase = (long)blockIdx.x * NSEQ;
    const int tid = threadIdx.x;
    const int warp = tid >> 5, lane = tid & 31;
    __shared__ float red[8];

    uint4 raw = ((const uint4*)(s + rbase))[tid];
    __half2 hx[4];
    hx[0] = *(__half2*)&raw.x; hx[1] = *(__half2*)&raw.y;
    hx[2] = *(__half2*)&raw.z; hx[3] = *(__half2*)&raw.w;
    float x[8];
    #pragma unroll
    for (int j = 0; j < 4; j++) {
        float2 f = __half22float2(hx[j]);
        x[2*j] = f.x; x[2*j+1] = f.y;
    }

    float m = x[0];
    #pragma unroll
    for (int j = 1; j < 8; j++) m = fmaxf(m, x[j]);
    #pragma unroll
    for (int o = 16; o > 0; o >>= 1) m = fmaxf(m, __shfl_xor_sync(0xFFFFFFFF, m, o));
    if (lane == 0) red[warp] = m;
    __syncthreads();
    m = red[lane & 7];
    #pragma unroll
    for (int o = 4; o > 0; o >>= 1) m = fmaxf(m, __shfl_xor_sync(0xFFFFFFFF, m, o));

    float sum = 0.f;
    #pragma unroll
    for (int j = 0; j < 8; j++) { x[j] = __expf(x[j] - m); sum += x[j]; }
    #pragma unroll
    for (int o = 16; o > 0; o >>= 1) sum += __shfl_xor_sync(0xFFFFFFFF, sum, o);
    __syncthreads();
    if (lane == 0) red[warp] = sum;
    __syncthreads();
    sum = red[lane & 7];
    #pragma unroll
    for (int o = 4; o > 0; o >>= 1) sum += __shfl_xor_sync(0xFFFFFFFF, sum, o);
    const float inv = 1.f / sum;

    __half2 h[4];
    #pragma unroll
    for (int j = 0; j < 4; j++) {
        h[j].x = __float2half(x[2*j]   * inv);
        h[j].y = __float2half(x[2*j+1] * inv);
    }
    uint4 outv;
    outv.x = *(uint32_t*)&h[0]; outv.y = *(uint32_t*)&h[1];
    outv.z = *(uint32_t*)&h[2]; outv.w = *(uint32_t*)&h[3];
    ((uint4*)(attn + rbase))[tid] = outv;
}

// ---------------- launch ----------------
extern "C" void kernel_launch(void* const* d_in, const int* in_sizes, int n_in,
                              void* d_out, int out_size)
{
    (void)in_sizes; (void)n_in; (void)out_size;
    const float* query   = (const float*)d_in[0];
    const float* context = (const float*)d_in[1];
    const float* Wq      = (const float*)d_in[2];
    const float* bq      = (const float*)d_in[3];
    const float* Wv      = (const float*)d_in[4];
    const float* bv      = (const float*)d_in[5];
    const float* Wo      = (const float*)d_in[6];
    const float* bo      = (const float*)d_in[7];
    float* out = (float*)d_out;

    __half *qry,*ctx,*wq,*wvT,*wo,*wp,*q,*uT,*attn,*s;
    float *b2;
    cudaGetSymbolAddress((void**)&qry, g_qry);
    cudaGetSymbolAddress((void**)&ctx, g_ctx);
    cudaGetSymbolAddress((void**)&wq,  g_wq);
    cudaGetSymbolAddress((void**)&wvT, g_wvT);
    cudaGetSymbolAddress((void**)&wo,  g_wo);
    cudaGetSymbolAddress((void**)&wp,  g_wp);
    cudaGetSymbolAddress((void**)&q,   g_q);
    cudaGetSymbolAddress((void**)&uT,  g_uT);
    cudaGetSymbolAddress((void**)&attn,g_attn);
    cudaGetSymbolAddress((void**)&s,   g_s);
    cudaGetSymbolAddress((void**)&b2,  g_b2);

    cudaFuncSetAttribute((const void*)mma_gemm<0>, cudaFuncAttributeMaxDynamicSharedMemorySize, SMEM_G);
    cudaFuncSetAttribute((const void*)mma_gemm<1>, cudaFuncAttributeMaxDynamicSharedMemorySize, SMEM_G);
    cudaFuncSetAttribute((const void*)u_gemm,      cudaFuncAttributeMaxDynamicSharedMemorySize, SMEM_G);

    // Side stream + fork/join events (created once; same enqueued work every call).
    static cudaStream_t s1 = nullptr;
    static cudaEvent_t evFork = nullptr, evJoin = nullptr;
    if (s1 == nullptr) {
        cudaStreamCreateWithFlags(&s1, cudaStreamNonBlocking);
        cudaEventCreateWithFlags(&evFork, cudaEventDisableTiming);
        cudaEventCreateWithFlags(&evJoin, cudaEventDisableTiming);
    }

    const float scale = 1.0f / sqrtf((float)DDIM);

    // 0) round all fp32 inputs -> fp16 (Wv written transposed)          [main stream]
    {
        int total = 2 * NQ4 + 3 * NW4;
        round_all_kernel<<<(total + 255) / 256, 256>>>(
            query, context, Wq, Wv, Wo,
            qry, ctx, wq, wvT, wo);
    }

    // fork: the u-branch (W', b'', u-proj) is independent of the QK chain
    cudaEventRecord(evFork, 0);
    cudaStreamWaitEvent(s1, evFork, 0);

    // --- side stream: W' = Wo@Wv ; b'' = Wo@bv + bo ; u^T = (ctx@W'^T)^T ---
    mma_gemm<1><<<dim3(DDIM/128, DDIM/128, 1), 256, SMEM_G, s1>>>(
        wo, wvT, nullptr, nullptr, wp,
        DDIM, DDIM, DDIM, 1.0f, 0, 0, 0);
    bias_fold_kernel<<<DDIM, 128, 0, s1>>>(Wo, bv, bo, b2);
    u_gemm<<<dim3(DDIM/128, MFLAT/128, 1), 256, SMEM_G, s1>>>(ctx, wp, uT);
    cudaEventRecord(evJoin, s1);

    // --- main stream: q-proj -> QK -> softmax ---
    // 1) q = round(qry @ Wq^T + bq)
    mma_gemm<1><<<dim3(DDIM/128, MFLAT/128, 1), 256, SMEM_G>>>(
        qry, wq, bq, nullptr, q,
        MFLAT, DDIM, DDIM, 1.0f, 0, 0, 0);

    // 2) scores = round_fp16(scale * q @ ctx^T)  (batched)
    mma_gemm<1><<<dim3(NSEQ/128, NSEQ/128, BB), 256, SMEM_G>>>(
        q, ctx, nullptr, nullptr, s,
        NSEQ, NSEQ, DDIM, scale,
        (long)NSEQ * DDIM, (long)NSEQ * DDIM, (long)NSEQ * NSEQ);

    // 3) softmax rows (fp16 in) -> rounded fp16 attn
    softmax_round_kernel<<<BB * NSEQ, 256>>>(s, attn);

    // join: AV needs u^T and b''
    cudaStreamWaitEvent(0, evJoin, 0);

    // 4) out = attn @ (u^T)^T + b''  (batched) -> fp32 out directly
    mma_gemm<0><<<dim3(DDIM/128, NSEQ/128, BB), 256, SMEM_G>>>(
        attn, uT, b2, out, nullptr,
        NSEQ, DDIM, NSEQ, 1.0f,
        (long)NSEQ * NSEQ, (long)DDIM * NSEQ, (long)NSEQ * DDIM);
}